// round 13
// baseline (speedup 1.0000x reference)
#include <cuda_runtime.h>
#include <cuda_fp16.h>
#include <math.h>

#define NB   4
#define CC   256
#define HH   128
#define WW   128
#define NPIX (HH*WW)            // 16384
#define NPIX_TOT (NB*NPIX)      // 65536
#define NPTS 5
#define G    4                  // channels per tile, interleaved half4 in smem (128 KB)
#define CG   (CC / G)           // 64
#define NTILES (NB * CG)        // 256
#define NCHUNK (NTILES * 16)    // 4096 chunks of 1024 pixels
#define GRID 148
#define SCALE 0.125f
// smem: sq[NPIX] uint2 (128 KB) + st1[NPIX] uint (64 KB) + st2[NPIX] ushort (32 KB)
#define SMEM_BYTES (NPIX*8 + NPIX*4 + NPIX*2)   // 229376 <= 232448

static __device__ __forceinline__ unsigned pack_h2(float a, float b) {
    half2 h = __floats2half2_rn(a, b);
    return *reinterpret_cast<unsigned*>(&h);
}
static __device__ __forceinline__ float2 unpack_h2(unsigned u) {
    half2 h = *reinterpret_cast<half2*>(&u);
    return __half22float2(h);
}

// Packed per-(n,h,w) sampling table, paired for wide loads:
//   g_t01[i] = {off0, w0, off1, w1}, g_t23[i] = {off2, w2, off3, w3}, g_t4[i] = {off4, w4}
// off = y_low*W + x_low (or -1 invalid), w = packed half2(lx, ly).
__device__ int4 g_t01[NPIX_TOT];
__device__ int4 g_t23[NPIX_TOT];
__device__ int2 g_t4 [NPIX_TOT];

__global__ void FR_precompute_kernel(const float* __restrict__ bb) {
    int i = blockIdx.x * blockDim.x + threadIdx.x;
    if (i >= NPIX_TOT) return;
    const float* b = bb + (size_t)i * 5;
    float cx = b[0], cy = b[1], w = b[2], h = b[3], t = b[4];
    float st, ct;
    sincosf(t, &st, &ct);
    float vx =  w * ct * 0.5f, vy = w * st * 0.5f;
    float wx = -h * st * 0.5f, wy = h * ct * 0.5f;

    float pxs[NPTS] = {cx, cx + vx + wx, cx - vx + wx, cx - vx - wx, cx + vx - wx};
    float pys[NPTS] = {cy, cy + vy + wy, cy - vy + wy, cy - vy - wy, cy + vy - wy};

    int offs[NPTS];
    int wpks[NPTS];
#pragma unroll
    for (int p = 0; p < NPTS; p++) {
        float x = pxs[p] * SCALE;
        float y = pys[p] * SCALE;
        bool valid = (y >= -1.0f) && (y <= (float)HH) && (x >= -1.0f) && (x <= (float)WW);
        y = fmaxf(y, 0.0f);
        x = fmaxf(x, 0.0f);
        int yl = min((int)floorf(y), HH - 1);
        int xl = min((int)floorf(x), WW - 1);
        if (yl >= HH - 1) y = (float)yl;   // mmcv border rule
        if (xl >= WW - 1) x = (float)xl;
        float ly = y - (float)yl;
        float lx = x - (float)xl;
        int off = yl * WW + xl;
        offs[p] = valid ? off : -1;
        wpks[p] = (int)pack_h2(lx, ly);
    }
    g_t01[i] = make_int4(offs[0], wpks[0], offs[1], wpks[1]);
    g_t23[i] = make_int4(offs[2], wpks[2], offs[3], wpks[3]);
    g_t4 [i] = make_int2(offs[4], wpks[4]);
}

// Decode one table entry: 4 smem offsets + 4 weights packed as two half2.
static __device__ __forceinline__ void decode_pt(int toff, int twpk, int o[4], unsigned wpk[2]) {
    float vf = (toff >= 0) ? 1.0f : 0.0f;
    int off = max(toff, 0);
    float2 l = unpack_h2((unsigned)twpk);
    float lx = l.x, ly = l.y;
    int xl = off & (WW - 1);
    int yl = off >> 7;
    int dx  = (xl < WW - 1) ? 1  : 0;
    int dyw = (yl < HH - 1) ? WW : 0;
    float hx = 1.0f - lx, hy = 1.0f - ly;
    wpk[0] = pack_h2(vf * hy * hx, vf * hy * lx);   // w00, w01
    wpk[1] = pack_h2(vf * ly * hx, vf * ly * lx);   // w10, w11
    o[0] = off; o[1] = off + dx; o[2] = off + dyw; o[3] = off + dyw + dx;
}

static __device__ __forceinline__ void fma_corner(float& a0, float& a1, float& a2, float& a3,
                                                  uint2 v, float w) {
    float2 c01 = unpack_h2(v.x);
    float2 c23 = unpack_h2(v.y);
    a0 += w * c01.x; a1 += w * c01.y; a2 += w * c23.x; a3 += w * c23.y;
}

static __device__ __forceinline__ void fma_pt(float& a0, float& a1, float& a2, float& a3,
                                              const uint2 v[4], const unsigned wpk[2]) {
    float2 wa = unpack_h2(wpk[0]);
    float2 wb = unpack_h2(wpk[1]);
    fma_corner(a0, a1, a2, a3, v[0], wa.x);
    fma_corner(a0, a1, a2, a3, v[1], wa.y);
    fma_corner(a0, a1, a2, a3, v[2], wb.x);
    fma_corner(a0, a1, a2, a3, v[3], wb.y);
}

// Persistent: 148 CTAs, one per SM, single wave. Work unit = 1024-pixel chunk
// (4096 total), contiguous per CTA. Channels 0-2 of the NEXT tile are staged
// into spare smem during the current tile's chunks (one slice per chunk), so
// the tile-switch fill collapses to a smem copy + ch3-only gmem read.
__global__ __launch_bounds__(1024, 1)
void FR_refine_kernel(const float* __restrict__ feat, float* __restrict__ out) {
    extern __shared__ unsigned int smem_raw[];
    uint2*          sq  = (uint2*)smem_raw;                         // 128 KB
    unsigned*       st1 = (unsigned*)(smem_raw + NPIX*2);           // 64 KB (ch0,ch1 packed)
    unsigned short* st2 = (unsigned short*)(smem_raw + NPIX*3);     // 32 KB (ch2 half bits)

    int c0 = (int)(((long long)blockIdx.x       * NCHUNK) / GRID);
    int c1 = (int)(((long long)(blockIdx.x + 1) * NCHUNK) / GRID);

    int cur_tile = -1;
    int stage_start = 16;            // slice from which next-tile staging is valid (16 = none)
    const float* f0 = feat;
    float*       ob = out;
    int tbase = 0;

    for (int c = c0; c < c1; c++) {
        int tile  = c >> 4;
        int slice = c & 15;
        if (tile != cur_tile) {
            f0 = feat + (size_t)tile * (G * NPIX);
            ob = out  + (size_t)tile * (G * NPIX);
            tbase = (tile >> 6) * NPIX;          // n * NPIX (CG = 64)

            __syncthreads();   // prior readers + staging writers done
            int sp = stage_start << 10;          // first staged pixel
            for (int q = threadIdx.x; q < NPIX; q += 1024) {
                uint2 pk;
                if (q >= sp) {
                    // staged: ch0-2 from smem, ch3 fresh from gmem
                    unsigned h3 = (unsigned)__half_as_ushort(__float2half_rn(f0[q + 3*NPIX]));
                    pk.x = st1[q];
                    pk.y = (unsigned)st2[q] | (h3 << 16);
                } else {
                    pk.x = pack_h2(f0[q],          f0[q + NPIX]);
                    pk.y = pack_h2(f0[q + 2*NPIX], f0[q + 3*NPIX]);
                }
                sq[q] = pk;
            }
            __syncthreads();

            cur_tile = tile;
            stage_start = slice;                 // staging of tile+1 begins at this slice
        }

        int pix = (slice << 10) + threadIdx.x;   // chunk-local, 1024-aligned
        int ti = tbase + pix;

        int4 e01 = g_t01[ti];
        int4 e23 = g_t23[ti];
        int2 e4  = g_t4 [ti];

        // residual: one conflict-free LDS.64 (fp16 identity term)
        uint2 rr = sq[pix];

        int oA[4], oB[4], oC[4];
        unsigned wA[2], wB[2], wC[2];
        decode_pt(e01.x, e01.y, oA, wA);
        decode_pt(e01.z, e01.w, oB, wB);
        decode_pt(e23.x, e23.y, oC, wC);

        uint2 vA[4], vB[4], vC[4];
#pragma unroll
        for (int k = 0; k < 4; k++) vA[k] = sq[oA[k]];
#pragma unroll
        for (int k = 0; k < 4; k++) vB[k] = sq[oB[k]];
#pragma unroll
        for (int k = 0; k < 4; k++) vC[k] = sq[oC[k]];

        int oD[4], oE[4];
        unsigned wD[2], wE[2];
        decode_pt(e23.z, e23.w, oD, wD);
        decode_pt(e4.x,  e4.y,  oE, wE);

        uint2 vD[4], vE[4];
#pragma unroll
        for (int k = 0; k < 4; k++) vD[k] = sq[oD[k]];
#pragma unroll
        for (int k = 0; k < 4; k++) vE[k] = sq[oE[k]];

        // stage this slice of the next tile (ch0-2), overlapped with the LDS body
        if (cur_tile + 1 < NTILES) {
            st1[pix] = pack_h2(f0[pix + 4*NPIX], f0[pix + 5*NPIX]);
            st2[pix] = __half_as_ushort(__float2half_rn(f0[pix + 6*NPIX]));
        }

        float2 r01 = unpack_h2(rr.x);
        float2 r23 = unpack_h2(rr.y);
        float a0 = r01.x, a1 = r01.y, a2 = r23.x, a3 = r23.y;
        fma_pt(a0, a1, a2, a3, vA, wA);
        fma_pt(a0, a1, a2, a3, vB, wB);
        fma_pt(a0, a1, a2, a3, vC, wC);
        fma_pt(a0, a1, a2, a3, vD, wD);
        fma_pt(a0, a1, a2, a3, vE, wE);

        ob[pix]            = a0;
        ob[pix + NPIX]     = a1;
        ob[pix + 2*NPIX]   = a2;
        ob[pix + 3*NPIX]   = a3;
    }
}

extern "C" void kernel_launch(void* const* d_in, const int* in_sizes, int n_in,
                              void* d_out, int out_size) {
    const float* feat = (const float*)d_in[0];  // [4,256,128,128] f32
    const float* bb   = (const float*)d_in[1];  // [4,128,128,5]   f32
    float*       out  = (float*)d_out;          // [4,256,128,128] f32

    FR_precompute_kernel<<<(NPIX_TOT + 255) / 256, 256>>>(bb);

    cudaFuncSetAttribute(FR_refine_kernel,
                         cudaFuncAttributeMaxDynamicSharedMemorySize, SMEM_BYTES);
    FR_refine_kernel<<<GRID, 1024, SMEM_BYTES>>>(feat, out);
}

// round 14
// speedup vs baseline: 1.0990x; 1.0990x over previous
#include <cuda_runtime.h>
#include <cuda_fp16.h>
#include <math.h>

#define NB   4
#define CC   256
#define HH   128
#define WW   128
#define NPIX (HH*WW)            // 16384
#define NPIX_TOT (NB*NPIX)      // 65536
#define NPTS 5
#define G    4                  // channels per tile, interleaved half4 in smem (128 KB)
#define CG   (CC / G)           // 64
#define NTILES (NB * CG)        // 256
#define CHUNKS_PER_TILE 16      // NPIX / 1024
#define NCHUNK (NTILES * CHUNKS_PER_TILE)   // 4096
#define GRID 148
#define SCALE 0.125f

static __device__ __forceinline__ unsigned pack_h2(float a, float b) {
    half2 h = __floats2half2_rn(a, b);
    return *reinterpret_cast<unsigned*>(&h);
}
static __device__ __forceinline__ float2 unpack_h2(unsigned u) {
    half2 h = *reinterpret_cast<half2*>(&u);
    return __half22float2(h);
}

// Packed per-(n,h,w) sampling table, paired for wide loads:
//   g_t01[i] = {off0, w0, off1, w1}, g_t23[i] = {off2, w2, off3, w3}, g_t4[i] = {off4, w4}
// off = y_low*W + x_low (or -1 invalid), w = packed half2(lx, ly).
__device__ int4 g_t01[NPIX_TOT];
__device__ int4 g_t23[NPIX_TOT];
__device__ int2 g_t4 [NPIX_TOT];

__global__ void FR_precompute_kernel(const float* __restrict__ bb) {
    int i = blockIdx.x * blockDim.x + threadIdx.x;
    if (i >= NPIX_TOT) return;
    const float* b = bb + (size_t)i * 5;
    float cx = b[0], cy = b[1], w = b[2], h = b[3], t = b[4];
    float st, ct;
    sincosf(t, &st, &ct);
    float vx =  w * ct * 0.5f, vy = w * st * 0.5f;
    float wx = -h * st * 0.5f, wy = h * ct * 0.5f;

    float pxs[NPTS] = {cx, cx + vx + wx, cx - vx + wx, cx - vx - wx, cx + vx - wx};
    float pys[NPTS] = {cy, cy + vy + wy, cy - vy + wy, cy - vy - wy, cy + vy - wy};

    int   offs[NPTS];
    int   wpks[NPTS];
#pragma unroll
    for (int p = 0; p < NPTS; p++) {
        float x = pxs[p] * SCALE;
        float y = pys[p] * SCALE;
        bool valid = (y >= -1.0f) && (y <= (float)HH) && (x >= -1.0f) && (x <= (float)WW);
        y = fmaxf(y, 0.0f);
        x = fmaxf(x, 0.0f);
        int yl = min((int)floorf(y), HH - 1);
        int xl = min((int)floorf(x), WW - 1);
        if (yl >= HH - 1) y = (float)yl;   // mmcv border rule
        if (xl >= WW - 1) x = (float)xl;
        float ly = y - (float)yl;
        float lx = x - (float)xl;
        int off = yl * WW + xl;
        offs[p] = valid ? off : -1;
        wpks[p] = (int)pack_h2(lx, ly);
    }
    g_t01[i] = make_int4(offs[0], wpks[0], offs[1], wpks[1]);
    g_t23[i] = make_int4(offs[2], wpks[2], offs[3], wpks[3]);
    g_t4 [i] = make_int2(offs[4], wpks[4]);
}

// Decode one table entry: 4 smem offsets + 4 weights packed as two half2.
static __device__ __forceinline__ void decode_pt(int toff, int twpk, int o[4], unsigned wpk[2]) {
    float vf = (toff >= 0) ? 1.0f : 0.0f;
    int off = max(toff, 0);
    float2 l = unpack_h2((unsigned)twpk);
    float lx = l.x, ly = l.y;
    int xl = off & (WW - 1);
    int yl = off >> 7;
    int dx  = (xl < WW - 1) ? 1  : 0;
    int dyw = (yl < HH - 1) ? WW : 0;
    float hx = 1.0f - lx, hy = 1.0f - ly;
    wpk[0] = pack_h2(vf * hy * hx, vf * hy * lx);   // w00, w01
    wpk[1] = pack_h2(vf * ly * hx, vf * ly * lx);   // w10, w11
    o[0] = off; o[1] = off + dx; o[2] = off + dyw; o[3] = off + dyw + dx;
}

static __device__ __forceinline__ void fma_corner(float& a0, float& a1, float& a2, float& a3,
                                                  uint2 v, float w) {
    float2 c01 = unpack_h2(v.x);
    float2 c23 = unpack_h2(v.y);
    a0 += w * c01.x; a1 += w * c01.y; a2 += w * c23.x; a3 += w * c23.y;
}

static __device__ __forceinline__ void fma_pt(float& a0, float& a1, float& a2, float& a3,
                                              const uint2 v[4], const unsigned wpk[2]) {
    float2 wa = unpack_h2(wpk[0]);
    float2 wb = unpack_h2(wpk[1]);
    fma_corner(a0, a1, a2, a3, v[0], wa.x);
    fma_corner(a0, a1, a2, a3, v[1], wa.y);
    fma_corner(a0, a1, a2, a3, v[2], wb.x);
    fma_corner(a0, a1, a2, a3, v[3], wb.y);
}

// Persistent: 148 CTAs, one per SM, single wave. Work unit = 1024-pixel chunk
// (4096 total), contiguous per CTA. Table entries for chunk c+1 are prefetched
// during chunk c's body so the ~240cyc L2 latency never gates the LDS block.
__global__ __launch_bounds__(1024, 1)
void FR_refine_kernel(const float* __restrict__ feat, float* __restrict__ out) {
    extern __shared__ unsigned int smem_raw[];
    uint2* sq = (uint2*)smem_raw;              // [NPIX] x packed half4

    int c0 = (int)(((long long)blockIdx.x       * NCHUNK) / GRID);
    int c1 = (int)(((long long)(blockIdx.x + 1) * NCHUNK) / GRID);

    int cur_tile = -1;
    const float* f0 = feat;
    float*       ob = out;

    // prime the table pipeline for chunk c0
    int ti0 = (((c0 >> 4) >> 6) * NPIX) + ((c0 & 15) << 10) + threadIdx.x;
    int4 e01 = g_t01[ti0];
    int4 e23 = g_t23[ti0];
    int2 e4  = g_t4 [ti0];

    for (int c = c0; c < c1; c++) {
        int tile = c >> 4;                      // CHUNKS_PER_TILE = 16
        if (tile != cur_tile) {
            cur_tile = tile;
            f0 = feat + (size_t)tile * (G * NPIX);
            ob = out  + (size_t)tile * (G * NPIX);

            __syncthreads();   // previous chunk's readers done before overwrite
            for (int q = threadIdx.x; q < NPIX; q += 1024) {
                uint2 pk;
                pk.x = pack_h2(f0[q],          f0[q + NPIX]);
                pk.y = pack_h2(f0[q + 2*NPIX], f0[q + 3*NPIX]);
                sq[q] = pk;
            }
            __syncthreads();
        }

        // prefetch chunk c+1's table entries (clamped at range end);
        // table lives in gmem, unaffected by smem refills between tiles.
        int cn = (c + 1 < c1) ? (c + 1) : c;
        int tin = (((cn >> 4) >> 6) * NPIX) + ((cn & 15) << 10) + threadIdx.x;
        int4 p01 = g_t01[tin];
        int4 p23 = g_t23[tin];
        int2 p4  = g_t4 [tin];

        int pix = ((c & 15) << 10) + threadIdx.x;   // chunk-local, 1024-aligned

        // residual: one conflict-free LDS.64 (fp16 identity term)
        uint2 rr = sq[pix];

        int oA[4], oB[4], oC[4];
        unsigned wA[2], wB[2], wC[2];
        decode_pt(e01.x, e01.y, oA, wA);
        decode_pt(e01.z, e01.w, oB, wB);
        decode_pt(e23.x, e23.y, oC, wC);

        uint2 vA[4], vB[4], vC[4];
#pragma unroll
        for (int k = 0; k < 4; k++) vA[k] = sq[oA[k]];
#pragma unroll
        for (int k = 0; k < 4; k++) vB[k] = sq[oB[k]];
#pragma unroll
        for (int k = 0; k < 4; k++) vC[k] = sq[oC[k]];

        int oD[4], oE[4];
        unsigned wD[2], wE[2];
        decode_pt(e23.z, e23.w, oD, wD);
        decode_pt(e4.x,  e4.y,  oE, wE);

        uint2 vD[4], vE[4];
#pragma unroll
        for (int k = 0; k < 4; k++) vD[k] = sq[oD[k]];
#pragma unroll
        for (int k = 0; k < 4; k++) vE[k] = sq[oE[k]];

        float2 r01 = unpack_h2(rr.x);
        float2 r23 = unpack_h2(rr.y);
        float a0 = r01.x, a1 = r01.y, a2 = r23.x, a3 = r23.y;
        fma_pt(a0, a1, a2, a3, vA, wA);
        fma_pt(a0, a1, a2, a3, vB, wB);
        fma_pt(a0, a1, a2, a3, vC, wC);
        fma_pt(a0, a1, a2, a3, vD, wD);
        fma_pt(a0, a1, a2, a3, vE, wE);

        ob[pix]            = a0;
        ob[pix + NPIX]     = a1;
        ob[pix + 2*NPIX]   = a2;
        ob[pix + 3*NPIX]   = a3;

        e01 = p01; e23 = p23; e4 = p4;
    }
}

extern "C" void kernel_launch(void* const* d_in, const int* in_sizes, int n_in,
                              void* d_out, int out_size) {
    const float* feat = (const float*)d_in[0];  // [4,256,128,128] f32
    const float* bb   = (const float*)d_in[1];  // [4,128,128,5]   f32
    float*       out  = (float*)d_out;          // [4,256,128,128] f32

    FR_precompute_kernel<<<(NPIX_TOT + 255) / 256, 256>>>(bb);

    size_t smem = (size_t)NPIX * 8;   // 131072 B
    cudaFuncSetAttribute(FR_refine_kernel,
                         cudaFuncAttributeMaxDynamicSharedMemorySize, (int)smem);
    FR_refine_kernel<<<GRID, 1024, smem>>>(feat, out);
}

// round 15
// speedup vs baseline: 1.1266x; 1.0251x over previous
#include <cuda_runtime.h>
#include <cuda_fp16.h>
#include <math.h>

#define NB   4
#define CC   256
#define HH   128
#define WW   128
#define NPIX (HH*WW)            // 16384
#define NPIX_TOT (NB*NPIX)      // 65536
#define NPTS 5
#define G    4                  // channels per tile, interleaved half4 in smem (128 KB)
#define CG   (CC / G)           // 64
#define NTILES (NB * CG)        // 256
#define CHUNKS_PER_TILE 16      // NPIX / 1024
#define NCHUNK (NTILES * CHUNKS_PER_TILE)   // 4096
#define GRID 148
#define SCALE 0.125f

static __device__ __forceinline__ unsigned pack_h2(float a, float b) {
    half2 h = __floats2half2_rn(a, b);
    return *reinterpret_cast<unsigned*>(&h);
}
static __device__ __forceinline__ float2 unpack_h2(unsigned u) {
    half2 h = *reinterpret_cast<half2*>(&u);
    return __half22float2(h);
}

// Packed per-(n,h,w) sampling table, paired for wide loads:
//   g_t01[i] = {off0, w0, off1, w1}, g_t23[i] = {off2, w2, off3, w3}, g_t4[i] = {off4, w4}
// off = y_low*W + x_low (or -1 invalid), w = packed half2(lx, ly).
__device__ int4 g_t01[NPIX_TOT];
__device__ int4 g_t23[NPIX_TOT];
__device__ int2 g_t4 [NPIX_TOT];

__global__ void FR_precompute_kernel(const float* __restrict__ bb) {
    int i = blockIdx.x * blockDim.x + threadIdx.x;
    if (i >= NPIX_TOT) return;
    const float* b = bb + (size_t)i * 5;
    float cx = b[0], cy = b[1], w = b[2], h = b[3], t = b[4];
    float st, ct;
    sincosf(t, &st, &ct);
    float vx =  w * ct * 0.5f, vy = w * st * 0.5f;
    float wx = -h * st * 0.5f, wy = h * ct * 0.5f;

    float pxs[NPTS] = {cx, cx + vx + wx, cx - vx + wx, cx - vx - wx, cx + vx - wx};
    float pys[NPTS] = {cy, cy + vy + wy, cy - vy + wy, cy - vy - wy, cy + vy - wy};

    int   offs[NPTS];
    int   wpks[NPTS];
#pragma unroll
    for (int p = 0; p < NPTS; p++) {
        float x = pxs[p] * SCALE;
        float y = pys[p] * SCALE;
        bool valid = (y >= -1.0f) && (y <= (float)HH) && (x >= -1.0f) && (x <= (float)WW);
        y = fmaxf(y, 0.0f);
        x = fmaxf(x, 0.0f);
        int yl = min((int)floorf(y), HH - 1);
        int xl = min((int)floorf(x), WW - 1);
        if (yl >= HH - 1) y = (float)yl;   // mmcv border rule
        if (xl >= WW - 1) x = (float)xl;
        float ly = y - (float)yl;
        float lx = x - (float)xl;
        int off = yl * WW + xl;
        offs[p] = valid ? off : -1;
        wpks[p] = (int)pack_h2(lx, ly);
    }
    g_t01[i] = make_int4(offs[0], wpks[0], offs[1], wpks[1]);
    g_t23[i] = make_int4(offs[2], wpks[2], offs[3], wpks[3]);
    g_t4 [i] = make_int2(offs[4], wpks[4]);
}

// Decode one table entry: 4 smem offsets + 4 weights packed as two half2.
static __device__ __forceinline__ void decode_pt(int toff, int twpk, int o[4], unsigned wpk[2]) {
    float vf = (toff >= 0) ? 1.0f : 0.0f;
    int off = max(toff, 0);
    float2 l = unpack_h2((unsigned)twpk);
    float lx = l.x, ly = l.y;
    int xl = off & (WW - 1);
    int yl = off >> 7;
    int dx  = (xl < WW - 1) ? 1  : 0;
    int dyw = (yl < HH - 1) ? WW : 0;
    float hx = 1.0f - lx, hy = 1.0f - ly;
    wpk[0] = pack_h2(vf * hy * hx, vf * hy * lx);   // w00, w01
    wpk[1] = pack_h2(vf * ly * hx, vf * ly * lx);   // w10, w11
    o[0] = off; o[1] = off + dx; o[2] = off + dyw; o[3] = off + dyw + dx;
}

static __device__ __forceinline__ void fma_corner(float& a0, float& a1, float& a2, float& a3,
                                                  uint2 v, float w) {
    float2 c01 = unpack_h2(v.x);
    float2 c23 = unpack_h2(v.y);
    a0 += w * c01.x; a1 += w * c01.y; a2 += w * c23.x; a3 += w * c23.y;
}

static __device__ __forceinline__ void fma_pt(float& a0, float& a1, float& a2, float& a3,
                                              const uint2 v[4], const unsigned wpk[2]) {
    float2 wa = unpack_h2(wpk[0]);
    float2 wb = unpack_h2(wpk[1]);
    fma_corner(a0, a1, a2, a3, v[0], wa.x);
    fma_corner(a0, a1, a2, a3, v[1], wa.y);
    fma_corner(a0, a1, a2, a3, v[2], wb.x);
    fma_corner(a0, a1, a2, a3, v[3], wb.y);
}

// Persistent: 148 CTAs, one per SM, single wave. Work unit = 1024-pixel chunk
// (4096 total), contiguous per CTA. Table entries for chunk c+1 are prefetched
// during chunk c's body; output stores use cache-streaming (evict-first) so the
// 64MB out stream doesn't evict feat/table lines needed by later tile fills.
__global__ __launch_bounds__(1024, 1)
void FR_refine_kernel(const float* __restrict__ feat, float* __restrict__ out) {
    extern __shared__ unsigned int smem_raw[];
    uint2* sq = (uint2*)smem_raw;              // [NPIX] x packed half4

    int c0 = (int)(((long long)blockIdx.x       * NCHUNK) / GRID);
    int c1 = (int)(((long long)(blockIdx.x + 1) * NCHUNK) / GRID);

    int cur_tile = -1;
    const float* f0 = feat;
    float*       ob = out;

    // prime the table pipeline for chunk c0
    int ti0 = (((c0 >> 4) >> 6) * NPIX) + ((c0 & 15) << 10) + threadIdx.x;
    int4 e01 = g_t01[ti0];
    int4 e23 = g_t23[ti0];
    int2 e4  = g_t4 [ti0];

    for (int c = c0; c < c1; c++) {
        int tile = c >> 4;                      // CHUNKS_PER_TILE = 16
        if (tile != cur_tile) {
            cur_tile = tile;
            f0 = feat + (size_t)tile * (G * NPIX);
            ob = out  + (size_t)tile * (G * NPIX);

            __syncthreads();   // previous chunk's readers done before overwrite
            for (int q = threadIdx.x; q < NPIX; q += 1024) {
                uint2 pk;
                pk.x = pack_h2(f0[q],          f0[q + NPIX]);
                pk.y = pack_h2(f0[q + 2*NPIX], f0[q + 3*NPIX]);
                sq[q] = pk;
            }
            __syncthreads();
        }

        // prefetch chunk c+1's table entries (clamped at range end);
        // table lives in gmem, unaffected by smem refills between tiles.
        int cn = (c + 1 < c1) ? (c + 1) : c;
        int tin = (((cn >> 4) >> 6) * NPIX) + ((cn & 15) << 10) + threadIdx.x;
        int4 p01 = g_t01[tin];
        int4 p23 = g_t23[tin];
        int2 p4  = g_t4 [tin];

        int pix = ((c & 15) << 10) + threadIdx.x;   // chunk-local, 1024-aligned

        // residual: one conflict-free LDS.64 (fp16 identity term)
        uint2 rr = sq[pix];

        int oA[4], oB[4], oC[4];
        unsigned wA[2], wB[2], wC[2];
        decode_pt(e01.x, e01.y, oA, wA);
        decode_pt(e01.z, e01.w, oB, wB);
        decode_pt(e23.x, e23.y, oC, wC);

        uint2 vA[4], vB[4], vC[4];
#pragma unroll
        for (int k = 0; k < 4; k++) vA[k] = sq[oA[k]];
#pragma unroll
        for (int k = 0; k < 4; k++) vB[k] = sq[oB[k]];
#pragma unroll
        for (int k = 0; k < 4; k++) vC[k] = sq[oC[k]];

        int oD[4], oE[4];
        unsigned wD[2], wE[2];
        decode_pt(e23.z, e23.w, oD, wD);
        decode_pt(e4.x,  e4.y,  oE, wE);

        uint2 vD[4], vE[4];
#pragma unroll
        for (int k = 0; k < 4; k++) vD[k] = sq[oD[k]];
#pragma unroll
        for (int k = 0; k < 4; k++) vE[k] = sq[oE[k]];

        float2 r01 = unpack_h2(rr.x);
        float2 r23 = unpack_h2(rr.y);
        float a0 = r01.x, a1 = r01.y, a2 = r23.x, a3 = r23.y;
        fma_pt(a0, a1, a2, a3, vA, wA);
        fma_pt(a0, a1, a2, a3, vB, wB);
        fma_pt(a0, a1, a2, a3, vC, wC);
        fma_pt(a0, a1, a2, a3, vD, wD);
        fma_pt(a0, a1, a2, a3, vE, wE);

        // streaming stores: evict-first, don't pollute L2 against feat/table
        __stcs(ob + pix,            a0);
        __stcs(ob + pix +   NPIX,   a1);
        __stcs(ob + pix + 2*NPIX,   a2);
        __stcs(ob + pix + 3*NPIX,   a3);

        e01 = p01; e23 = p23; e4 = p4;
    }
}

extern "C" void kernel_launch(void* const* d_in, const int* in_sizes, int n_in,
                              void* d_out, int out_size) {
    const float* feat = (const float*)d_in[0];  // [4,256,128,128] f32
    const float* bb   = (const float*)d_in[1];  // [4,128,128,5]   f32
    float*       out  = (float*)d_out;          // [4,256,128,128] f32

    FR_precompute_kernel<<<(NPIX_TOT + 255) / 256, 256>>>(bb);

    size_t smem = (size_t)NPIX * 8;   // 131072 B
    cudaFuncSetAttribute(FR_refine_kernel,
                         cudaFuncAttributeMaxDynamicSharedMemorySize, (int)smem);
    FR_refine_kernel<<<GRID, 1024, smem>>>(feat, out);
}